// round 9
// baseline (speedup 1.0000x reference)
#include <cuda_runtime.h>
#include <cuda_bf16.h>
#include <math.h>

#define NN 100000
#define EE 1600000

// ---------------- scratch ----------------
__device__ float g_h [NN * 128];
__device__ float g_xl[NN * 128];
__device__ float g_xr[NN * 128];
__device__ __nv_bfloat16 g_ah[NN * 128];      // A hi (x or hn)
__device__ __nv_bfloat16 g_al[NN * 128];      // A lo
__device__ __nv_bfloat16 g_wh[5 * 128 * 128]; // weights hi, transposed [n][k]
__device__ __nv_bfloat16 g_wl[5 * 128 * 128]; // weights lo
__device__ int g_cnt[NN];
__device__ int g_cur[NN];
__device__ int g_offs[NN + 1];
__device__ int g_esrc[EE + NN];

// bf16 split helpers
__device__ __forceinline__ void splitbf(float v, unsigned short& h, unsigned short& l) {
    __nv_bfloat16 hb = __float2bfloat16_rn(v);
    h = __bfloat16_as_ushort(hb);
    l = __bfloat16_as_ushort(__float2bfloat16_rn(v - __bfloat162float(hb)));
}

// ---------------- CSR build ----------------
__global__ void zero_cnt_kernel() {
    int i = blockIdx.x * blockDim.x + threadIdx.x;
    if (i < NN) g_cnt[i] = 0;
}
__global__ void hist_kernel(const int* __restrict__ ei) {
    int e = blockIdx.x * blockDim.x + threadIdx.x;
    if (e < EE) atomicAdd(&g_cnt[ei[EE + e]], 1);
}
__global__ void scan_kernel() {
    __shared__ int sh[1024];
    const int CH = 98;
    int t = threadIdx.x;
    int start = t * CH;
    int s = 0;
    for (int j = 0; j < CH; j++) {
        int idx = start + j;
        if (idx < NN) s += g_cnt[idx] + 1;
    }
    sh[t] = s;
    __syncthreads();
    for (int off = 1; off < 1024; off <<= 1) {
        int u = (t >= off) ? sh[t - off] : 0;
        __syncthreads();
        sh[t] += u;
        __syncthreads();
    }
    int run = (t == 0) ? 0 : sh[t - 1];
    for (int j = 0; j < CH; j++) {
        int idx = start + j;
        if (idx >= NN) break;
        int v = g_cnt[idx] + 1;
        g_cur[idx] = run;
        run += v;
        g_offs[idx + 1] = run;
    }
    if (t == 0) g_offs[0] = 0;
}
// scatter real edges; the extra NN tail threads write self-loops into segment ends
__global__ void scatter_kernel(const int* __restrict__ ei) {
    int e = blockIdx.x * blockDim.x + threadIdx.x;
    if (e < EE) {
        int s = ei[e];
        int d = ei[EE + e];
        int p = atomicAdd(&g_cur[d], 1);
        g_esrc[p] = s;
    } else if (e < EE + NN) {
        int i = e - EE;
        g_esrc[g_offs[i + 1] - 1] = i;   // self-loop in last slot of segment
    }
}

// ---------------- weight convert: transpose + bf16 split ----------------
__global__ void convert_w_kernel(const float* __restrict__ Wp, const float* __restrict__ Wl,
                                 const float* __restrict__ Wr) {
    int i = blockIdx.x * blockDim.x + threadIdx.x;
    if (i >= 5 * 16384) return;
    int s = i >> 14, r = i & 16383;
    int n = r >> 7, k = r & 127;
    const float* src;
    if (s == 0) src = Wp;
    else if (s == 1) src = Wl;
    else if (s == 2) src = Wr;
    else if (s == 3) src = Wl + 16384;
    else src = Wr + 16384;
    float v = src[k * 128 + n];   // transpose -> [n][k]
    unsigned short h, l;
    splitbf(v, h, l);
    g_wh[i] = __ushort_as_bfloat16(h);
    g_wl[i] = __ushort_as_bfloat16(l);
}

// ---------------- x convert: fp32 -> bf16 hi/lo ----------------
__global__ void convert_x_kernel(const float* __restrict__ x) {
    int i = blockIdx.x * blockDim.x + threadIdx.x;   // float4 index
    if (i >= NN * 32) return;
    float4 v = ((const float4*)x)[i];
    unsigned short h0, l0, h1, l1, h2, l2, h3, l3;
    splitbf(v.x, h0, l0); splitbf(v.y, h1, l1); splitbf(v.z, h2, l2); splitbf(v.w, h3, l3);
    uint2 hh, ll;
    hh.x = (unsigned)h0 | ((unsigned)h1 << 16);
    hh.y = (unsigned)h2 | ((unsigned)h3 << 16);
    ll.x = (unsigned)l0 | ((unsigned)l1 << 16);
    ll.y = (unsigned)l2 | ((unsigned)l3 << 16);
    ((uint2*)g_ah)[i] = hh;
    ((uint2*)g_al)[i] = ll;
}

// ---------------- LayerNorm fused with bf16 split: g_h -> g_ah/g_al ----------------
__global__ void ln_kernel(const float* __restrict__ gamma, const float* __restrict__ beta) {
    int gw = (blockIdx.x * blockDim.x + threadIdx.x) >> 5;
    int lane = threadIdx.x & 31;
    if (gw >= NN) return;
    float4 h4 = ((const float4*)g_h)[(size_t)gw * 32 + lane];
    float s = h4.x + h4.y + h4.z + h4.w;
    float ss = h4.x * h4.x + h4.y * h4.y + h4.z * h4.z + h4.w * h4.w;
#pragma unroll
    for (int o = 16; o > 0; o >>= 1) {
        s  += __shfl_xor_sync(0xffffffffu, s, o);
        ss += __shfl_xor_sync(0xffffffffu, ss, o);
    }
    float mu = s * (1.f / 128.f);
    float var = ss * (1.f / 128.f) - mu * mu;
    float rs = rsqrtf(var + 1e-5f);
    float4 g4 = ((const float4*)gamma)[lane];
    float4 b4 = ((const float4*)beta)[lane];
    float o0 = (h4.x - mu) * rs * g4.x + b4.x;
    float o1 = (h4.y - mu) * rs * g4.y + b4.y;
    float o2 = (h4.z - mu) * rs * g4.z + b4.z;
    float o3 = (h4.w - mu) * rs * g4.w + b4.w;
    unsigned short h0, l0, h1, l1, h2, l2, h3, l3;
    splitbf(o0, h0, l0); splitbf(o1, h1, l1); splitbf(o2, h2, l2); splitbf(o3, h3, l3);
    uint2 hh, ll;
    hh.x = (unsigned)h0 | ((unsigned)h1 << 16);
    hh.y = (unsigned)h2 | ((unsigned)h3 << 16);
    ll.x = (unsigned)l0 | ((unsigned)l1 << 16);
    ll.y = (unsigned)l2 | ((unsigned)l3 << 16);
    ((uint2*)g_ah)[(size_t)gw * 32 + lane] = hh;
    ((uint2*)g_al)[(size_t)gw * 32 + lane] = ll;
}

// ---------------- mma.sync split-bf16 GEMM: C[M,128] = A[M,128] @ W^T + bias ----
// 256 threads = 8 warps in 2(M) x 4(N); warp tile 64x32; full K=128 in smem.
#define SPAD 136            // padded row stride in bf16 elems (272 B)
#define SMAT (128 * SPAD)   // elems per matrix

__device__ __forceinline__ void mma16816(float* c, unsigned a0, unsigned a1, unsigned a2,
                                         unsigned a3, unsigned b0, unsigned b1) {
    asm volatile(
        "mma.sync.aligned.m16n8k16.row.col.f32.bf16.bf16.f32 "
        "{%0,%1,%2,%3}, {%4,%5,%6,%7}, {%8,%9}, {%0,%1,%2,%3};"
        : "+f"(c[0]), "+f"(c[1]), "+f"(c[2]), "+f"(c[3])
        : "r"(a0), "r"(a1), "r"(a2), "r"(a3), "r"(b0), "r"(b1));
}

__global__ void __launch_bounds__(256, 1)
mma_gemm_kernel(int wslot, const float* __restrict__ bias, int csel) {
    extern __shared__ __nv_bfloat16 sm[];
    __nv_bfloat16* sAh = sm;
    __nv_bfloat16* sAl = sm + SMAT;
    __nv_bfloat16* sBh = sm + 2 * SMAT;
    __nv_bfloat16* sBl = sm + 3 * SMAT;

    int tid = threadIdx.x, wid = tid >> 5, lane = tid & 31;
    int m0 = blockIdx.x * 128;
    const __nv_bfloat16* Bh = g_wh + wslot * 16384;
    const __nv_bfloat16* Bl = g_wl + wslot * 16384;
    float* C = (csel == 0) ? g_h : ((csel == 1) ? g_xl : g_xr);

    // stage tiles (row-major, padded rows)
    const uint4 z4 = make_uint4(0, 0, 0, 0);
    for (int i = tid; i < 2048; i += 256) {
        int row = i >> 4, c8 = i & 15;
        int so = row * SPAD + c8 * 8;
        int gr = m0 + row;
        uint4 vh = z4, vl = z4;
        if (gr < NN) {
            vh = *(const uint4*)(g_ah + (size_t)gr * 128 + c8 * 8);
            vl = *(const uint4*)(g_al + (size_t)gr * 128 + c8 * 8);
        }
        *(uint4*)(sAh + so) = vh;
        *(uint4*)(sAl + so) = vl;
        *(uint4*)(sBh + so) = *(const uint4*)(Bh + row * 128 + c8 * 8);
        *(uint4*)(sBl + so) = *(const uint4*)(Bl + row * 128 + c8 * 8);
    }
    __syncthreads();

    int wm = wid >> 2, wn = wid & 3;
    int g = lane >> 2, tg = lane & 3;

    float acc[4][4][4];
#pragma unroll
    for (int mf = 0; mf < 4; mf++)
#pragma unroll
        for (int nf = 0; nf < 4; nf++)
#pragma unroll
            for (int j = 0; j < 4; j++) acc[mf][nf][j] = 0.f;

    int arow = wm * 64 + g;
    int brow = wn * 32 + g;
    int kbase = tg * 2;

#pragma unroll 2
    for (int ks = 0; ks < 8; ks++) {
        int kk = ks * 16 + kbase;
        unsigned bh[4][2], bl[4][2];
#pragma unroll
        for (int nf = 0; nf < 4; nf++) {
            int ro = (brow + nf * 8) * SPAD + kk;
            bh[nf][0] = *(const unsigned*)(sBh + ro);
            bh[nf][1] = *(const unsigned*)(sBh + ro + 8);
            bl[nf][0] = *(const unsigned*)(sBl + ro);
            bl[nf][1] = *(const unsigned*)(sBl + ro + 8);
        }
#pragma unroll
        for (int mf = 0; mf < 4; mf++) {
            int ro = (arow + mf * 16) * SPAD + kk;
            unsigned ah0 = *(const unsigned*)(sAh + ro);
            unsigned ah1 = *(const unsigned*)(sAh + ro + 8 * SPAD);
            unsigned ah2 = *(const unsigned*)(sAh + ro + 8);
            unsigned ah3 = *(const unsigned*)(sAh + ro + 8 * SPAD + 8);
            unsigned al0 = *(const unsigned*)(sAl + ro);
            unsigned al1 = *(const unsigned*)(sAl + ro + 8 * SPAD);
            unsigned al2 = *(const unsigned*)(sAl + ro + 8);
            unsigned al3 = *(const unsigned*)(sAl + ro + 8 * SPAD + 8);
#pragma unroll
            for (int nf = 0; nf < 4; nf++) {
                mma16816(acc[mf][nf], ah0, ah1, ah2, ah3, bh[nf][0], bh[nf][1]);
                mma16816(acc[mf][nf], ah0, ah1, ah2, ah3, bl[nf][0], bl[nf][1]);
                mma16816(acc[mf][nf], al0, al1, al2, al3, bh[nf][0], bh[nf][1]);
            }
        }
    }

    // epilogue: add bias, store fp32
#pragma unroll
    for (int nf = 0; nf < 4; nf++) {
        int col = wn * 32 + nf * 8 + tg * 2;
        float b0 = bias[col], b1 = bias[col + 1];
#pragma unroll
        for (int mf = 0; mf < 4; mf++) {
            int r0 = m0 + wm * 64 + mf * 16 + g;
            if (r0 < NN) {
                float2 v0 = make_float2(acc[mf][nf][0] + b0, acc[mf][nf][1] + b1);
                *(float2*)(C + (size_t)r0 * 128 + col) = v0;
            }
            int r1 = r0 + 8;
            if (r1 < NN) {
                float2 v1 = make_float2(acc[mf][nf][2] + b0, acc[mf][nf][3] + b1);
                *(float2*)(C + (size_t)r1 * 128 + col) = v1;
            }
        }
    }
}

// ---------------- fused GATv2 attention + aggregation (warp per dst node) ------
__global__ void edge_kernel(const float* __restrict__ att, const float* __restrict__ gb) {
    int gw = (blockIdx.x * blockDim.x + threadIdx.x) >> 5;
    int lane = threadIdx.x & 31;
    if (gw >= NN) return;
    int off = g_offs[gw], end = g_offs[gw + 1];
    const float4* xl4 = (const float4*)g_xl;
    float4 xr = ((const float4*)g_xr)[(size_t)gw * 32 + lane];
    float4 at = ((const float4*)att)[lane];

    float m = -1e30f, ssum = 0.f;
    float4 acc = make_float4(0.f, 0.f, 0.f, 0.f);

    int e = off;
    if ((end - off) & 1) {
        int s0 = g_esrc[e];
        float4 x0 = xl4[(size_t)s0 * 32 + lane];
        float m0 = x0.x + xr.x, m1 = x0.y + xr.y, m2 = x0.z + xr.z, m3 = x0.w + xr.w;
        float p = ((m0 > 0.f) ? m0 : 0.2f * m0) * at.x + ((m1 > 0.f) ? m1 : 0.2f * m1) * at.y
                + ((m2 > 0.f) ? m2 : 0.2f * m2) * at.z + ((m3 > 0.f) ? m3 : 0.2f * m3) * at.w;
        p += __shfl_xor_sync(0xffffffffu, p, 1);
        p += __shfl_xor_sync(0xffffffffu, p, 2);
        p += __shfl_xor_sync(0xffffffffu, p, 4);
        m = p;
        ssum = 1.f;
        acc = x0;
        e++;
    }
    for (; e < end; e += 2) {
        int s0 = g_esrc[e], s1 = g_esrc[e + 1];
        float4 x0 = xl4[(size_t)s0 * 32 + lane];
        float4 x1 = xl4[(size_t)s1 * 32 + lane];
        float a0 = x0.x + xr.x, a1 = x0.y + xr.y, a2 = x0.z + xr.z, a3 = x0.w + xr.w;
        float b0 = x1.x + xr.x, b1 = x1.y + xr.y, b2 = x1.z + xr.z, b3 = x1.w + xr.w;
        float p0 = ((a0 > 0.f) ? a0 : 0.2f * a0) * at.x + ((a1 > 0.f) ? a1 : 0.2f * a1) * at.y
                 + ((a2 > 0.f) ? a2 : 0.2f * a2) * at.z + ((a3 > 0.f) ? a3 : 0.2f * a3) * at.w;
        float p1 = ((b0 > 0.f) ? b0 : 0.2f * b0) * at.x + ((b1 > 0.f) ? b1 : 0.2f * b1) * at.y
                 + ((b2 > 0.f) ? b2 : 0.2f * b2) * at.z + ((b3 > 0.f) ? b3 : 0.2f * b3) * at.w;
        p0 += __shfl_xor_sync(0xffffffffu, p0, 1);
        p1 += __shfl_xor_sync(0xffffffffu, p1, 1);
        p0 += __shfl_xor_sync(0xffffffffu, p0, 2);
        p1 += __shfl_xor_sync(0xffffffffu, p1, 2);
        p0 += __shfl_xor_sync(0xffffffffu, p0, 4);
        p1 += __shfl_xor_sync(0xffffffffu, p1, 4);
        float nm = fmaxf(m, fmaxf(p0, p1));
        float corr = __expf(m - nm);
        float w0 = __expf(p0 - nm);
        float w1 = __expf(p1 - nm);
        ssum = ssum * corr + w0 + w1;
        acc.x = acc.x * corr + w0 * x0.x + w1 * x1.x;
        acc.y = acc.y * corr + w0 * x0.y + w1 * x1.y;
        acc.z = acc.z * corr + w0 * x0.z + w1 * x1.z;
        acc.w = acc.w * corr + w0 * x0.w + w1 * x1.w;
        m = nm;
    }
    float inv = 1.f / ssum;
    float4 gb4 = ((const float4*)gb)[lane];
    float4 id = ((const float4*)g_h)[(size_t)gw * 32 + lane];
    float4 o;
    o.x = fmaxf(acc.x * inv + gb4.x, 0.f) + id.x;
    o.y = fmaxf(acc.y * inv + gb4.y, 0.f) + id.y;
    o.z = fmaxf(acc.z * inv + gb4.z, 0.f) + id.z;
    o.w = fmaxf(acc.w * inv + gb4.w, 0.f) + id.w;
    ((float4*)g_h)[(size_t)gw * 32 + lane] = o;
}

// ---------------- fused classification + h copy (warp per row) ----------------
__global__ void class_copy_kernel(const float* __restrict__ Wc, const float* __restrict__ bc,
                                  float* __restrict__ out) {
    __shared__ float sWc[128 * 16];
    __shared__ float sbc[16];
    int t = threadIdx.x;
    for (int i = t; i < 2048; i += 256) sWc[i] = Wc[i];
    if (t < 16) sbc[t] = bc[t];
    __syncthreads();

    int gw = (blockIdx.x * blockDim.x + t) >> 5;
    int lane = t & 31;
    if (gw >= NN) return;
    float4 h4 = ((const float4*)g_h)[(size_t)gw * 32 + lane];
    // copy h to second output region (coalesced, read g_h only once)
    ((float4*)(out + (size_t)NN * 16))[(size_t)gw * 32 + lane] = h4;

    float p[16];
    const float* w0 = sWc + (lane * 4 + 0) * 16;
    const float* w1 = sWc + (lane * 4 + 1) * 16;
    const float* w2 = sWc + (lane * 4 + 2) * 16;
    const float* w3 = sWc + (lane * 4 + 3) * 16;
#pragma unroll
    for (int j = 0; j < 16; j++)
        p[j] = h4.x * w0[j] + h4.y * w1[j] + h4.z * w2[j] + h4.w * w3[j];
#pragma unroll
    for (int sh = 16; sh > 0; sh >>= 1)
#pragma unroll
        for (int j = 0; j < 16; j++)
            p[j] += __shfl_xor_sync(0xffffffffu, p[j], sh);
    if (lane < 16) out[(size_t)gw * 16 + lane] = p[lane] + sbc[lane];
}

// ---------------- launcher ----------------
extern "C" void kernel_launch(void* const* d_in, const int* in_sizes, int n_in,
                              void* d_out, int out_size) {
    const float* x    = (const float*)d_in[0];
    const int*   ei   = (const int*)  d_in[1];
    const float* Wp   = (const float*)d_in[2];
    const float* bp   = (const float*)d_in[3];
    const float* ln_g = (const float*)d_in[4];
    const float* ln_b = (const float*)d_in[5];
    const float* Wl   = (const float*)d_in[6];
    const float* bl   = (const float*)d_in[7];
    const float* Wr   = (const float*)d_in[8];
    const float* br   = (const float*)d_in[9];
    const float* att  = (const float*)d_in[10];
    const float* gb   = (const float*)d_in[11];
    const float* Wc   = (const float*)d_in[12];
    const float* bc   = (const float*)d_in[13];
    float* out = (float*)d_out;

    const int SMEM_BYTES = 4 * SMAT * 2;   // 139264 B
    cudaFuncSetAttribute(mma_gemm_kernel, cudaFuncAttributeMaxDynamicSharedMemorySize, SMEM_BYTES);

    // CSR by destination (self-loops folded into scatter grid tail)
    zero_cnt_kernel<<<(NN + 255) / 256, 256>>>();
    hist_kernel<<<EE / 256, 256>>>(ei);
    scan_kernel<<<1, 1024>>>();
    scatter_kernel<<<(EE + NN + 255) / 256, 256>>>(ei);

    // weight + input conversion
    convert_w_kernel<<<(5 * 16384 + 255) / 256, 256>>>(Wp, Wl, Wr);
    convert_x_kernel<<<(NN * 32 + 255) / 256, 256>>>(x);

    const int GG = (NN + 127) / 128;
    // h = x @ Wp + bp
    mma_gemm_kernel<<<GG, 256, SMEM_BYTES>>>(0, bp, 0);

    for (int l = 0; l < 2; l++) {
        ln_kernel<<<(NN * 32 + 255) / 256, 256>>>(ln_g + l * 128, ln_b + l * 128);
        mma_gemm_kernel<<<GG, 256, SMEM_BYTES>>>(1 + 2 * l, bl + l * 128, 1);
        mma_gemm_kernel<<<GG, 256, SMEM_BYTES>>>(2 + 2 * l, br + l * 128, 2);
        edge_kernel<<<(NN * 32 + 255) / 256, 256>>>(att + l * 128, gb + l * 128);
    }

    class_copy_kernel<<<(NN * 32 + 255) / 256, 256>>>(Wc, bc, out);
}

// round 11
// speedup vs baseline: 1.6655x; 1.6655x over previous
#include <cuda_runtime.h>
#include <cuda_bf16.h>
#include <math.h>

#define NN 100000
#define EE 1600000

// ---------------- scratch ----------------
__device__ float g_h [NN * 128];
__device__ float g_xl[NN * 128];
__device__ float g_xr[NN * 128];
__device__ __nv_bfloat16 g_ah[NN * 128];      // A hi (x or hn)
__device__ __nv_bfloat16 g_al[NN * 128];      // A lo
__device__ __nv_bfloat16 g_wh[5 * 128 * 128]; // weights hi, transposed [n][k]
__device__ __nv_bfloat16 g_wl[5 * 128 * 128]; // weights lo
__device__ int g_cnt[NN];
__device__ int g_cur[NN];
__device__ int g_offs[NN + 1];
__device__ int g_esrc[EE + NN];

// bf16 split helpers
__device__ __forceinline__ void splitbf(float v, unsigned short& h, unsigned short& l) {
    __nv_bfloat16 hb = __float2bfloat16_rn(v);
    h = __bfloat16_as_ushort(hb);
    l = __bfloat16_as_ushort(__float2bfloat16_rn(v - __bfloat162float(hb)));
}

// ---------------- CSR build ----------------
__global__ void zero_cnt_kernel() {
    int i = blockIdx.x * blockDim.x + threadIdx.x;
    if (i < NN) g_cnt[i] = 0;
}
__global__ void hist_kernel(const int* __restrict__ ei) {
    int e = blockIdx.x * blockDim.x + threadIdx.x;
    if (e < EE) atomicAdd(&g_cnt[ei[EE + e]], 1);
}
__global__ void scan_kernel() {
    __shared__ int sh[1024];
    const int CH = 98;
    int t = threadIdx.x;
    int start = t * CH;
    int s = 0;
    for (int j = 0; j < CH; j++) {
        int idx = start + j;
        if (idx < NN) s += g_cnt[idx] + 1;
    }
    sh[t] = s;
    __syncthreads();
    for (int off = 1; off < 1024; off <<= 1) {
        int u = (t >= off) ? sh[t - off] : 0;
        __syncthreads();
        sh[t] += u;
        __syncthreads();
    }
    int run = (t == 0) ? 0 : sh[t - 1];
    for (int j = 0; j < CH; j++) {
        int idx = start + j;
        if (idx >= NN) break;
        int v = g_cnt[idx] + 1;
        g_cur[idx] = run;
        run += v;
        g_offs[idx + 1] = run;
    }
    if (t == 0) g_offs[0] = 0;
}
__global__ void scatter_kernel(const int* __restrict__ ei) {
    int e = blockIdx.x * blockDim.x + threadIdx.x;
    if (e < EE) {
        int s = ei[e];
        int d = ei[EE + e];
        int p = atomicAdd(&g_cur[d], 1);
        g_esrc[p] = s;
    }
}
__global__ void selfloop_kernel() {
    int i = blockIdx.x * blockDim.x + threadIdx.x;
    if (i < NN) g_esrc[g_offs[i + 1] - 1] = i;
}

// ---------------- weight convert: transpose + bf16 split ----------------
__global__ void convert_w_kernel(const float* __restrict__ Wp, const float* __restrict__ Wl,
                                 const float* __restrict__ Wr) {
    int i = blockIdx.x * blockDim.x + threadIdx.x;
    if (i >= 5 * 16384) return;
    int s = i >> 14, r = i & 16383;
    int n = r >> 7, k = r & 127;
    const float* src;
    if (s == 0) src = Wp;
    else if (s == 1) src = Wl;
    else if (s == 2) src = Wr;
    else if (s == 3) src = Wl + 16384;
    else src = Wr + 16384;
    float v = src[k * 128 + n];   // transpose -> [n][k]
    unsigned short h, l;
    splitbf(v, h, l);
    g_wh[i] = __ushort_as_bfloat16(h);
    g_wl[i] = __ushort_as_bfloat16(l);
}

// ---------------- x convert: fp32 -> bf16 hi/lo ----------------
__global__ void convert_x_kernel(const float* __restrict__ x) {
    int i = blockIdx.x * blockDim.x + threadIdx.x;   // float4 index
    if (i >= NN * 32) return;
    float4 v = ((const float4*)x)[i];
    unsigned short h0, l0, h1, l1, h2, l2, h3, l3;
    splitbf(v.x, h0, l0); splitbf(v.y, h1, l1); splitbf(v.z, h2, l2); splitbf(v.w, h3, l3);
    uint2 hh, ll;
    hh.x = (unsigned)h0 | ((unsigned)h1 << 16);
    hh.y = (unsigned)h2 | ((unsigned)h3 << 16);
    ll.x = (unsigned)l0 | ((unsigned)l1 << 16);
    ll.y = (unsigned)l2 | ((unsigned)l3 << 16);
    ((uint2*)g_ah)[i] = hh;
    ((uint2*)g_al)[i] = ll;
}

// ---------------- LayerNorm fused with bf16 split: g_h -> g_ah/g_al ----------------
__global__ void ln_kernel(const float* __restrict__ gamma, const float* __restrict__ beta) {
    int gw = (blockIdx.x * blockDim.x + threadIdx.x) >> 5;
    int lane = threadIdx.x & 31;
    if (gw >= NN) return;
    float4 h4 = ((const float4*)g_h)[(size_t)gw * 32 + lane];
    float s = h4.x + h4.y + h4.z + h4.w;
    float ss = h4.x * h4.x + h4.y * h4.y + h4.z * h4.z + h4.w * h4.w;
#pragma unroll
    for (int o = 16; o > 0; o >>= 1) {
        s  += __shfl_xor_sync(0xffffffffu, s, o);
        ss += __shfl_xor_sync(0xffffffffu, ss, o);
    }
    float mu = s * (1.f / 128.f);
    float var = ss * (1.f / 128.f) - mu * mu;
    float rs = rsqrtf(var + 1e-5f);
    float4 g4 = ((const float4*)gamma)[lane];
    float4 b4 = ((const float4*)beta)[lane];
    float o0 = (h4.x - mu) * rs * g4.x + b4.x;
    float o1 = (h4.y - mu) * rs * g4.y + b4.y;
    float o2 = (h4.z - mu) * rs * g4.z + b4.z;
    float o3 = (h4.w - mu) * rs * g4.w + b4.w;
    unsigned short h0, l0, h1, l1, h2, l2, h3, l3;
    splitbf(o0, h0, l0); splitbf(o1, h1, l1); splitbf(o2, h2, l2); splitbf(o3, h3, l3);
    uint2 hh, ll;
    hh.x = (unsigned)h0 | ((unsigned)h1 << 16);
    hh.y = (unsigned)h2 | ((unsigned)h3 << 16);
    ll.x = (unsigned)l0 | ((unsigned)l1 << 16);
    ll.y = (unsigned)l2 | ((unsigned)l3 << 16);
    ((uint2*)g_ah)[(size_t)gw * 32 + lane] = hh;
    ((uint2*)g_al)[(size_t)gw * 32 + lane] = ll;
}

// ---------------- mma.sync split-bf16 GEMM: C[M,128] = A[M,128] @ W^T + bias ----
// 256 threads = 8 warps in 2(M) x 4(N); warp tile 64x32; full K=128 in smem.
#define SPAD 136            // padded row stride in bf16 elems (272 B)
#define SMAT (128 * SPAD)   // elems per matrix

__device__ __forceinline__ void mma16816(float* c, unsigned a0, unsigned a1, unsigned a2,
                                         unsigned a3, unsigned b0, unsigned b1) {
    asm volatile(
        "mma.sync.aligned.m16n8k16.row.col.f32.bf16.bf16.f32 "
        "{%0,%1,%2,%3}, {%4,%5,%6,%7}, {%8,%9}, {%0,%1,%2,%3};"
        : "+f"(c[0]), "+f"(c[1]), "+f"(c[2]), "+f"(c[3])
        : "r"(a0), "r"(a1), "r"(a2), "r"(a3), "r"(b0), "r"(b1));
}

__global__ void __launch_bounds__(256, 1)
mma_gemm_kernel(int wslot, const float* __restrict__ bias, int csel) {
    extern __shared__ __nv_bfloat16 sm[];
    __nv_bfloat16* sAh = sm;
    __nv_bfloat16* sAl = sm + SMAT;
    __nv_bfloat16* sBh = sm + 2 * SMAT;
    __nv_bfloat16* sBl = sm + 3 * SMAT;

    int tid = threadIdx.x, wid = tid >> 5, lane = tid & 31;
    int m0 = blockIdx.x * 128;
    const __nv_bfloat16* Bh = g_wh + wslot * 16384;
    const __nv_bfloat16* Bl = g_wl + wslot * 16384;
    float* C = (csel == 0) ? g_h : ((csel == 1) ? g_xl : g_xr);

    // stage tiles (row-major, padded rows)
    const uint4 z4 = make_uint4(0, 0, 0, 0);
    for (int i = tid; i < 2048; i += 256) {
        int row = i >> 4, c8 = i & 15;
        int so = row * SPAD + c8 * 8;
        int gr = m0 + row;
        uint4 vh = z4, vl = z4;
        if (gr < NN) {
            vh = *(const uint4*)(g_ah + (size_t)gr * 128 + c8 * 8);
            vl = *(const uint4*)(g_al + (size_t)gr * 128 + c8 * 8);
        }
        *(uint4*)(sAh + so) = vh;
        *(uint4*)(sAl + so) = vl;
        *(uint4*)(sBh + so) = *(const uint4*)(Bh + row * 128 + c8 * 8);
        *(uint4*)(sBl + so) = *(const uint4*)(Bl + row * 128 + c8 * 8);
    }
    __syncthreads();

    int wm = wid >> 2, wn = wid & 3;
    int g = lane >> 2, tg = lane & 3;

    float acc[4][4][4];
#pragma unroll
    for (int mf = 0; mf < 4; mf++)
#pragma unroll
        for (int nf = 0; nf < 4; nf++)
#pragma unroll
            for (int j = 0; j < 4; j++) acc[mf][nf][j] = 0.f;

    int arow = wm * 64 + g;
    int brow = wn * 32 + g;
    int kbase = tg * 2;

#pragma unroll 2
    for (int ks = 0; ks < 8; ks++) {
        int kk = ks * 16 + kbase;
        unsigned bh[4][2], bl[4][2];
#pragma unroll
        for (int nf = 0; nf < 4; nf++) {
            int ro = (brow + nf * 8) * SPAD + kk;
            bh[nf][0] = *(const unsigned*)(sBh + ro);
            bh[nf][1] = *(const unsigned*)(sBh + ro + 8);
            bl[nf][0] = *(const unsigned*)(sBl + ro);
            bl[nf][1] = *(const unsigned*)(sBl + ro + 8);
        }
#pragma unroll
        for (int mf = 0; mf < 4; mf++) {
            int ro = (arow + mf * 16) * SPAD + kk;
            unsigned ah0 = *(const unsigned*)(sAh + ro);
            unsigned ah1 = *(const unsigned*)(sAh + ro + 8 * SPAD);
            unsigned ah2 = *(const unsigned*)(sAh + ro + 8);
            unsigned ah3 = *(const unsigned*)(sAh + ro + 8 * SPAD + 8);
            unsigned al0 = *(const unsigned*)(sAl + ro);
            unsigned al1 = *(const unsigned*)(sAl + ro + 8 * SPAD);
            unsigned al2 = *(const unsigned*)(sAl + ro + 8);
            unsigned al3 = *(const unsigned*)(sAl + ro + 8 * SPAD + 8);
#pragma unroll
            for (int nf = 0; nf < 4; nf++) {
                mma16816(acc[mf][nf], ah0, ah1, ah2, ah3, bh[nf][0], bh[nf][1]);
                mma16816(acc[mf][nf], ah0, ah1, ah2, ah3, bl[nf][0], bl[nf][1]);
                mma16816(acc[mf][nf], al0, al1, al2, al3, bh[nf][0], bh[nf][1]);
            }
        }
    }

    // epilogue: add bias, store fp32
#pragma unroll
    for (int nf = 0; nf < 4; nf++) {
        int col = wn * 32 + nf * 8 + tg * 2;
        float b0 = bias[col], b1 = bias[col + 1];
#pragma unroll
        for (int mf = 0; mf < 4; mf++) {
            int r0 = m0 + wm * 64 + mf * 16 + g;
            if (r0 < NN) {
                float2 v0 = make_float2(acc[mf][nf][0] + b0, acc[mf][nf][1] + b1);
                *(float2*)(C + (size_t)r0 * 128 + col) = v0;
            }
            int r1 = r0 + 8;
            if (r1 < NN) {
                float2 v1 = make_float2(acc[mf][nf][2] + b0, acc[mf][nf][3] + b1);
                *(float2*)(C + (size_t)r1 * 128 + col) = v1;
            }
        }
    }
}

// ---------------- fused GATv2 attention + aggregation (warp per dst node) ------
__global__ void edge_kernel(const float* __restrict__ att, const float* __restrict__ gb) {
    int gw = (blockIdx.x * blockDim.x + threadIdx.x) >> 5;
    int lane = threadIdx.x & 31;
    if (gw >= NN) return;
    int off = g_offs[gw], end = g_offs[gw + 1];
    const float4* xl4 = (const float4*)g_xl;
    float4 xr = ((const float4*)g_xr)[(size_t)gw * 32 + lane];
    float4 at = ((const float4*)att)[lane];

    float m = -1e30f, ssum = 0.f;
    float4 acc = make_float4(0.f, 0.f, 0.f, 0.f);

    int e = off;
    if ((end - off) & 1) {
        int s0 = g_esrc[e];
        float4 x0 = xl4[(size_t)s0 * 32 + lane];
        float m0 = x0.x + xr.x, m1 = x0.y + xr.y, m2 = x0.z + xr.z, m3 = x0.w + xr.w;
        float p = ((m0 > 0.f) ? m0 : 0.2f * m0) * at.x + ((m1 > 0.f) ? m1 : 0.2f * m1) * at.y
                + ((m2 > 0.f) ? m2 : 0.2f * m2) * at.z + ((m3 > 0.f) ? m3 : 0.2f * m3) * at.w;
        p += __shfl_xor_sync(0xffffffffu, p, 1);
        p += __shfl_xor_sync(0xffffffffu, p, 2);
        p += __shfl_xor_sync(0xffffffffu, p, 4);
        m = p;
        ssum = 1.f;
        acc = x0;
        e++;
    }
    for (; e < end; e += 2) {
        int s0 = g_esrc[e], s1 = g_esrc[e + 1];
        float4 x0 = xl4[(size_t)s0 * 32 + lane];
        float4 x1 = xl4[(size_t)s1 * 32 + lane];
        float a0 = x0.x + xr.x, a1 = x0.y + xr.y, a2 = x0.z + xr.z, a3 = x0.w + xr.w;
        float b0 = x1.x + xr.x, b1 = x1.y + xr.y, b2 = x1.z + xr.z, b3 = x1.w + xr.w;
        float p0 = ((a0 > 0.f) ? a0 : 0.2f * a0) * at.x + ((a1 > 0.f) ? a1 : 0.2f * a1) * at.y
                 + ((a2 > 0.f) ? a2 : 0.2f * a2) * at.z + ((a3 > 0.f) ? a3 : 0.2f * a3) * at.w;
        float p1 = ((b0 > 0.f) ? b0 : 0.2f * b0) * at.x + ((b1 > 0.f) ? b1 : 0.2f * b1) * at.y
                 + ((b2 > 0.f) ? b2 : 0.2f * b2) * at.z + ((b3 > 0.f) ? b3 : 0.2f * b3) * at.w;
        p0 += __shfl_xor_sync(0xffffffffu, p0, 1);
        p1 += __shfl_xor_sync(0xffffffffu, p1, 1);
        p0 += __shfl_xor_sync(0xffffffffu, p0, 2);
        p1 += __shfl_xor_sync(0xffffffffu, p1, 2);
        p0 += __shfl_xor_sync(0xffffffffu, p0, 4);
        p1 += __shfl_xor_sync(0xffffffffu, p1, 4);
        float nm = fmaxf(m, fmaxf(p0, p1));
        float corr = __expf(m - nm);
        float w0 = __expf(p0 - nm);
        float w1 = __expf(p1 - nm);
        ssum = ssum * corr + w0 + w1;
        acc.x = acc.x * corr + w0 * x0.x + w1 * x1.x;
        acc.y = acc.y * corr + w0 * x0.y + w1 * x1.y;
        acc.z = acc.z * corr + w0 * x0.z + w1 * x1.z;
        acc.w = acc.w * corr + w0 * x0.w + w1 * x1.w;
        m = nm;
    }
    float inv = 1.f / ssum;
    float4 gb4 = ((const float4*)gb)[lane];
    float4 id = ((const float4*)g_h)[(size_t)gw * 32 + lane];
    float4 o;
    o.x = fmaxf(acc.x * inv + gb4.x, 0.f) + id.x;
    o.y = fmaxf(acc.y * inv + gb4.y, 0.f) + id.y;
    o.z = fmaxf(acc.z * inv + gb4.z, 0.f) + id.z;
    o.w = fmaxf(acc.w * inv + gb4.w, 0.f) + id.w;
    ((float4*)g_h)[(size_t)gw * 32 + lane] = o;
}

// ---------------- fused classification + h copy (warp per row, conflict-free) ----
// sW is transposed: sW[j][k] = Wc[k][j]; lane reads sW[j][lane*4 .. lane*4+3]
// as one LDS.128 -> per 8-lane phase covers contiguous 128B: zero bank conflicts.
__global__ void class_copy_kernel(const float* __restrict__ Wc, const float* __restrict__ bc,
                                  float* __restrict__ out) {
    __shared__ float sW[16][128];
    __shared__ float sbc[16];
    int t = threadIdx.x;
    for (int i = t; i < 2048; i += 256) {
        int k = i >> 4, j = i & 15;
        sW[j][k] = Wc[i];          // Wc row-major [k][j]
    }
    if (t < 16) sbc[t] = bc[t];
    __syncthreads();

    int gw = (blockIdx.x * blockDim.x + t) >> 5;
    int lane = t & 31;
    if (gw >= NN) return;
    float4 h4 = ((const float4*)g_h)[(size_t)gw * 32 + lane];
    // copy h to second output region (coalesced; g_h read exactly once)
    ((float4*)(out + (size_t)NN * 16))[(size_t)gw * 32 + lane] = h4;

    float p[16];
#pragma unroll
    for (int j = 0; j < 16; j++) {
        float4 w = *(const float4*)&sW[j][lane * 4];
        p[j] = h4.x * w.x + h4.y * w.y + h4.z * w.z + h4.w * w.w;
    }
#pragma unroll
    for (int sh = 16; sh > 0; sh >>= 1)
#pragma unroll
        for (int j = 0; j < 16; j++)
            p[j] += __shfl_xor_sync(0xffffffffu, p[j], sh);
    if (lane < 16) out[(size_t)gw * 16 + lane] = p[lane] + sbc[lane];
}

// ---------------- launcher ----------------
extern "C" void kernel_launch(void* const* d_in, const int* in_sizes, int n_in,
                              void* d_out, int out_size) {
    const float* x    = (const float*)d_in[0];
    const int*   ei   = (const int*)  d_in[1];
    const float* Wp   = (const float*)d_in[2];
    const float* bp   = (const float*)d_in[3];
    const float* ln_g = (const float*)d_in[4];
    const float* ln_b = (const float*)d_in[5];
    const float* Wl   = (const float*)d_in[6];
    const float* bl   = (const float*)d_in[7];
    const float* Wr   = (const float*)d_in[8];
    const float* br   = (const float*)d_in[9];
    const float* att  = (const float*)d_in[10];
    const float* gb   = (const float*)d_in[11];
    const float* Wc   = (const float*)d_in[12];
    const float* bc   = (const float*)d_in[13];
    float* out = (float*)d_out;

    const int SMEM_BYTES = 4 * SMAT * 2;   // 139264 B
    cudaFuncSetAttribute(mma_gemm_kernel, cudaFuncAttributeMaxDynamicSharedMemorySize, SMEM_BYTES);

    // CSR by destination (round-5 structure)
    zero_cnt_kernel<<<(NN + 255) / 256, 256>>>();
    hist_kernel<<<EE / 256, 256>>>(ei);
    scan_kernel<<<1, 1024>>>();
    scatter_kernel<<<EE / 256, 256>>>(ei);
    selfloop_kernel<<<(NN + 255) / 256, 256>>>();

    // weight + input conversion
    convert_w_kernel<<<(5 * 16384 + 255) / 256, 256>>>(Wp, Wl, Wr);
    convert_x_kernel<<<(NN * 32 + 255) / 256, 256>>>(x);

    const int GG = (NN + 127) / 128;
    // h = x @ Wp + bp
    mma_gemm_kernel<<<GG, 256, SMEM_BYTES>>>(0, bp, 0);

    for (int l = 0; l < 2; l++) {
        ln_kernel<<<(NN * 32 + 255) / 256, 256>>>(ln_g + l * 128, ln_b + l * 128);
        mma_gemm_kernel<<<GG, 256, SMEM_BYTES>>>(1 + 2 * l, bl + l * 128, 1);
        mma_gemm_kernel<<<GG, 256, SMEM_BYTES>>>(2 + 2 * l, br + l * 128, 2);
        edge_kernel<<<(NN * 32 + 255) / 256, 256>>>(att + l * 128, gb + l * 128);
    }

    class_copy_kernel<<<(NN * 32 + 255) / 256, 256>>>(Wc, bc, out);
}

// round 12
// speedup vs baseline: 2.1019x; 1.2620x over previous
#include <cuda_runtime.h>
#include <cuda_bf16.h>
#include <cuda_fp16.h>
#include <math.h>

#define NN 100000
#define EE 1600000
#define SCAN_B 391   // ceil(NN/256)

// ---------------- scratch ----------------
__device__ float g_h [NN * 128];
__device__ __half g_xlh[NN * 128];            // x_l stored fp16 (gather table)
__device__ float g_xr[NN * 128];
__device__ __nv_bfloat16 g_ah[NN * 128];      // A hi (x or hn)
__device__ __nv_bfloat16 g_al[NN * 128];      // A lo
__device__ __nv_bfloat16 g_wh[5 * 128 * 128]; // weights hi, transposed [n][k]
__device__ __nv_bfloat16 g_wl[5 * 128 * 128]; // weights lo
__device__ int g_cnt[NN];
__device__ int g_cur[NN];
__device__ int g_offs[NN + 1];
__device__ int g_esrc[EE + NN];
__device__ int g_bsum[SCAN_B];
__device__ int g_boff[SCAN_B];

// bf16 split helpers
__device__ __forceinline__ void splitbf(float v, unsigned short& h, unsigned short& l) {
    __nv_bfloat16 hb = __float2bfloat16_rn(v);
    h = __bfloat16_as_ushort(hb);
    l = __bfloat16_as_ushort(__float2bfloat16_rn(v - __bfloat162float(hb)));
}

// ---------------- CSR build ----------------
__global__ void zero_cnt_kernel() {
    int i = blockIdx.x * blockDim.x + threadIdx.x;
    if (i < NN) g_cnt[i] = 0;
}
__global__ void hist_kernel(const int* __restrict__ ei) {
    int e = blockIdx.x * blockDim.x + threadIdx.x;
    if (e < EE) atomicAdd(&g_cnt[ei[EE + e]], 1);
}
// 3-pass coalesced scan of (cnt[i]+1)
__global__ void scan1_kernel() {
    __shared__ int sh[256];
    int t = threadIdx.x;
    int i = blockIdx.x * 256 + t;
    sh[t] = (i < NN) ? g_cnt[i] + 1 : 0;
    __syncthreads();
    for (int o = 128; o > 0; o >>= 1) {
        if (t < o) sh[t] += sh[t + o];
        __syncthreads();
    }
    if (t == 0) g_bsum[blockIdx.x] = sh[0];
}
__global__ void scan2_kernel() {
    __shared__ int sh[512];
    int t = threadIdx.x;
    sh[t] = (t < SCAN_B) ? g_bsum[t] : 0;
    __syncthreads();
    for (int o = 1; o < 512; o <<= 1) {
        int u = (t >= o) ? sh[t - o] : 0;
        __syncthreads();
        sh[t] += u;
        __syncthreads();
    }
    if (t < SCAN_B) g_boff[t] = (t == 0) ? 0 : sh[t - 1];
}
__global__ void scan3_kernel() {
    __shared__ int sh[256];
    int t = threadIdx.x;
    int i = blockIdx.x * 256 + t;
    int v = (i < NN) ? g_cnt[i] + 1 : 0;
    sh[t] = v;
    __syncthreads();
    for (int o = 1; o < 256; o <<= 1) {
        int u = (t >= o) ? sh[t - o] : 0;
        __syncthreads();
        sh[t] += u;
        __syncthreads();
    }
    if (i < NN) {
        int incl = sh[t] + g_boff[blockIdx.x];
        g_cur[i] = incl - v;          // segment start (scatter cursor)
        g_offs[i + 1] = incl;
        g_esrc[incl - 1] = i;         // self-loop in last slot of segment
        if (i == 0) g_offs[0] = 0;
    }
}
__global__ void scatter_kernel(const int* __restrict__ ei) {
    int e = blockIdx.x * blockDim.x + threadIdx.x;
    if (e < EE) {
        int s = ei[e];
        int d = ei[EE + e];
        int p = atomicAdd(&g_cur[d], 1);
        g_esrc[p] = s;
    }
}

// ---------------- weight convert: transpose + bf16 split ----------------
__global__ void convert_w_kernel(const float* __restrict__ Wp, const float* __restrict__ Wl,
                                 const float* __restrict__ Wr) {
    int i = blockIdx.x * blockDim.x + threadIdx.x;
    if (i >= 5 * 16384) return;
    int s = i >> 14, r = i & 16383;
    int n = r >> 7, k = r & 127;
    const float* src;
    if (s == 0) src = Wp;
    else if (s == 1) src = Wl;
    else if (s == 2) src = Wr;
    else if (s == 3) src = Wl + 16384;
    else src = Wr + 16384;
    float v = src[k * 128 + n];   // transpose -> [n][k]
    unsigned short h, l;
    splitbf(v, h, l);
    g_wh[i] = __ushort_as_bfloat16(h);
    g_wl[i] = __ushort_as_bfloat16(l);
}

// ---------------- x convert: fp32 -> bf16 hi/lo ----------------
__global__ void convert_x_kernel(const float* __restrict__ x) {
    int i = blockIdx.x * blockDim.x + threadIdx.x;   // float4 index
    if (i >= NN * 32) return;
    float4 v = ((const float4*)x)[i];
    unsigned short h0, l0, h1, l1, h2, l2, h3, l3;
    splitbf(v.x, h0, l0); splitbf(v.y, h1, l1); splitbf(v.z, h2, l2); splitbf(v.w, h3, l3);
    uint2 hh, ll;
    hh.x = (unsigned)h0 | ((unsigned)h1 << 16);
    hh.y = (unsigned)h2 | ((unsigned)h3 << 16);
    ll.x = (unsigned)l0 | ((unsigned)l1 << 16);
    ll.y = (unsigned)l2 | ((unsigned)l3 << 16);
    ((uint2*)g_ah)[i] = hh;
    ((uint2*)g_al)[i] = ll;
}

// ---------------- LayerNorm fused with bf16 split: g_h -> g_ah/g_al ----------------
__global__ void ln_kernel(const float* __restrict__ gamma, const float* __restrict__ beta) {
    int gw = (blockIdx.x * blockDim.x + threadIdx.x) >> 5;
    int lane = threadIdx.x & 31;
    if (gw >= NN) return;
    float4 h4 = ((const float4*)g_h)[(size_t)gw * 32 + lane];
    float s = h4.x + h4.y + h4.z + h4.w;
    float ss = h4.x * h4.x + h4.y * h4.y + h4.z * h4.z + h4.w * h4.w;
#pragma unroll
    for (int o = 16; o > 0; o >>= 1) {
        s  += __shfl_xor_sync(0xffffffffu, s, o);
        ss += __shfl_xor_sync(0xffffffffu, ss, o);
    }
    float mu = s * (1.f / 128.f);
    float var = ss * (1.f / 128.f) - mu * mu;
    float rs = rsqrtf(var + 1e-5f);
    float4 g4 = ((const float4*)gamma)[lane];
    float4 b4 = ((const float4*)beta)[lane];
    float o0 = (h4.x - mu) * rs * g4.x + b4.x;
    float o1 = (h4.y - mu) * rs * g4.y + b4.y;
    float o2 = (h4.z - mu) * rs * g4.z + b4.z;
    float o3 = (h4.w - mu) * rs * g4.w + b4.w;
    unsigned short h0, l0, h1, l1, h2, l2, h3, l3;
    splitbf(o0, h0, l0); splitbf(o1, h1, l1); splitbf(o2, h2, l2); splitbf(o3, h3, l3);
    uint2 hh, ll;
    hh.x = (unsigned)h0 | ((unsigned)h1 << 16);
    hh.y = (unsigned)h2 | ((unsigned)h3 << 16);
    ll.x = (unsigned)l0 | ((unsigned)l1 << 16);
    ll.y = (unsigned)l2 | ((unsigned)l3 << 16);
    ((uint2*)g_ah)[(size_t)gw * 32 + lane] = hh;
    ((uint2*)g_al)[(size_t)gw * 32 + lane] = ll;
}

// ---------------- mma.sync split-bf16 GEMM: C[M,128] = A[M,128] @ W^T + bias ----
// 256 threads = 8 warps in 2(M) x 4(N); warp tile 64x32; full K=128 in smem.
// csel: 0 -> g_h (fp32), 1 -> g_xlh (fp16!), 2 -> g_xr (fp32)
#define SPAD 136            // padded row stride in bf16 elems (272 B)
#define SMAT (128 * SPAD)   // elems per matrix

__device__ __forceinline__ void mma16816(float* c, unsigned a0, unsigned a1, unsigned a2,
                                         unsigned a3, unsigned b0, unsigned b1) {
    asm volatile(
        "mma.sync.aligned.m16n8k16.row.col.f32.bf16.bf16.f32 "
        "{%0,%1,%2,%3}, {%4,%5,%6,%7}, {%8,%9}, {%0,%1,%2,%3};"
        : "+f"(c[0]), "+f"(c[1]), "+f"(c[2]), "+f"(c[3])
        : "r"(a0), "r"(a1), "r"(a2), "r"(a3), "r"(b0), "r"(b1));
}

__global__ void __launch_bounds__(256, 1)
mma_gemm_kernel(int wslot, const float* __restrict__ bias, int csel) {
    extern __shared__ __nv_bfloat16 sm[];
    __nv_bfloat16* sAh = sm;
    __nv_bfloat16* sAl = sm + SMAT;
    __nv_bfloat16* sBh = sm + 2 * SMAT;
    __nv_bfloat16* sBl = sm + 3 * SMAT;

    int tid = threadIdx.x, wid = tid >> 5, lane = tid & 31;
    int m0 = blockIdx.x * 128;
    const __nv_bfloat16* Bh = g_wh + wslot * 16384;
    const __nv_bfloat16* Bl = g_wl + wslot * 16384;

    // stage tiles (row-major, padded rows)
    const uint4 z4 = make_uint4(0, 0, 0, 0);
    for (int i = tid; i < 2048; i += 256) {
        int row = i >> 4, c8 = i & 15;
        int so = row * SPAD + c8 * 8;
        int gr = m0 + row;
        uint4 vh = z4, vl = z4;
        if (gr < NN) {
            vh = *(const uint4*)(g_ah + (size_t)gr * 128 + c8 * 8);
            vl = *(const uint4*)(g_al + (size_t)gr * 128 + c8 * 8);
        }
        *(uint4*)(sAh + so) = vh;
        *(uint4*)(sAl + so) = vl;
        *(uint4*)(sBh + so) = *(const uint4*)(Bh + row * 128 + c8 * 8);
        *(uint4*)(sBl + so) = *(const uint4*)(Bl + row * 128 + c8 * 8);
    }
    __syncthreads();

    int wm = wid >> 2, wn = wid & 3;
    int g = lane >> 2, tg = lane & 3;

    float acc[4][4][4];
#pragma unroll
    for (int mf = 0; mf < 4; mf++)
#pragma unroll
        for (int nf = 0; nf < 4; nf++)
#pragma unroll
            for (int j = 0; j < 4; j++) acc[mf][nf][j] = 0.f;

    int arow = wm * 64 + g;
    int brow = wn * 32 + g;
    int kbase = tg * 2;

#pragma unroll 2
    for (int ks = 0; ks < 8; ks++) {
        int kk = ks * 16 + kbase;
        unsigned bh[4][2], bl[4][2];
#pragma unroll
        for (int nf = 0; nf < 4; nf++) {
            int ro = (brow + nf * 8) * SPAD + kk;
            bh[nf][0] = *(const unsigned*)(sBh + ro);
            bh[nf][1] = *(const unsigned*)(sBh + ro + 8);
            bl[nf][0] = *(const unsigned*)(sBl + ro);
            bl[nf][1] = *(const unsigned*)(sBl + ro + 8);
        }
#pragma unroll
        for (int mf = 0; mf < 4; mf++) {
            int ro = (arow + mf * 16) * SPAD + kk;
            unsigned ah0 = *(const unsigned*)(sAh + ro);
            unsigned ah1 = *(const unsigned*)(sAh + ro + 8 * SPAD);
            unsigned ah2 = *(const unsigned*)(sAh + ro + 8);
            unsigned ah3 = *(const unsigned*)(sAh + ro + 8 * SPAD + 8);
            unsigned al0 = *(const unsigned*)(sAl + ro);
            unsigned al1 = *(const unsigned*)(sAl + ro + 8 * SPAD);
            unsigned al2 = *(const unsigned*)(sAl + ro + 8);
            unsigned al3 = *(const unsigned*)(sAl + ro + 8 * SPAD + 8);
#pragma unroll
            for (int nf = 0; nf < 4; nf++) {
                mma16816(acc[mf][nf], ah0, ah1, ah2, ah3, bh[nf][0], bh[nf][1]);
                mma16816(acc[mf][nf], ah0, ah1, ah2, ah3, bl[nf][0], bl[nf][1]);
                mma16816(acc[mf][nf], al0, al1, al2, al3, bh[nf][0], bh[nf][1]);
            }
        }
    }

    // epilogue: add bias, store (fp16 for x_l, fp32 otherwise)
    if (csel == 1) {
        __half2* H = (__half2*)g_xlh;   // index: row*64 + col/2
#pragma unroll
        for (int nf = 0; nf < 4; nf++) {
            int col = wn * 32 + nf * 8 + tg * 2;
            float b0 = bias[col], b1 = bias[col + 1];
#pragma unroll
            for (int mf = 0; mf < 4; mf++) {
                int r0 = m0 + wm * 64 + mf * 16 + g;
                if (r0 < NN)
                    H[(size_t)r0 * 64 + (col >> 1)] =
                        __floats2half2_rn(acc[mf][nf][0] + b0, acc[mf][nf][1] + b1);
                int r1 = r0 + 8;
                if (r1 < NN)
                    H[(size_t)r1 * 64 + (col >> 1)] =
                        __floats2half2_rn(acc[mf][nf][2] + b0, acc[mf][nf][3] + b1);
            }
        }
    } else {
        float* C = (csel == 0) ? g_h : g_xr;
#pragma unroll
        for (int nf = 0; nf < 4; nf++) {
            int col = wn * 32 + nf * 8 + tg * 2;
            float b0 = bias[col], b1 = bias[col + 1];
#pragma unroll
            for (int mf = 0; mf < 4; mf++) {
                int r0 = m0 + wm * 64 + mf * 16 + g;
                if (r0 < NN) {
                    float2 v0 = make_float2(acc[mf][nf][0] + b0, acc[mf][nf][1] + b1);
                    *(float2*)(C + (size_t)r0 * 128 + col) = v0;
                }
                int r1 = r0 + 8;
                if (r1 < NN) {
                    float2 v1 = make_float2(acc[mf][nf][2] + b0, acc[mf][nf][3] + b1);
                    *(float2*)(C + (size_t)r1 * 128 + col) = v1;
                }
            }
        }
    }
}

// ---------------- fused GATv2 attention + aggregation (warp per dst node) ------
// x_l gathered as fp16 (256 B/edge instead of 512 B)
__device__ __forceinline__ float4 load_xl(const uint2* __restrict__ xlh, int src, int lane) {
    uint2 r = xlh[(size_t)src * 32 + lane];
    float2 f01 = __half22float2(*reinterpret_cast<__half2*>(&r.x));
    float2 f23 = __half22float2(*reinterpret_cast<__half2*>(&r.y));
    return make_float4(f01.x, f01.y, f23.x, f23.y);
}

__global__ void edge_kernel(const float* __restrict__ att, const float* __restrict__ gb) {
    int gw = (blockIdx.x * blockDim.x + threadIdx.x) >> 5;
    int lane = threadIdx.x & 31;
    if (gw >= NN) return;
    int off = g_offs[gw], end = g_offs[gw + 1];
    const uint2* xlh = (const uint2*)g_xlh;
    float4 xr = ((const float4*)g_xr)[(size_t)gw * 32 + lane];
    float4 at = ((const float4*)att)[lane];

    float m = -1e30f, ssum = 0.f;
    float4 acc = make_float4(0.f, 0.f, 0.f, 0.f);

    int e = off;
    if ((end - off) & 1) {
        float4 x0 = load_xl(xlh, g_esrc[e], lane);
        float m0 = x0.x + xr.x, m1 = x0.y + xr.y, m2 = x0.z + xr.z, m3 = x0.w + xr.w;
        float p = ((m0 > 0.f) ? m0 : 0.2f * m0) * at.x + ((m1 > 0.f) ? m1 : 0.2f * m1) * at.y
                + ((m2 > 0.f) ? m2 : 0.2f * m2) * at.z + ((m3 > 0.f) ? m3 : 0.2f * m3) * at.w;
        p += __shfl_xor_sync(0xffffffffu, p, 1);
        p += __shfl_xor_sync(0xffffffffu, p, 2);
        p += __shfl_xor_sync(0xffffffffu, p, 4);
        m = p;
        ssum = 1.f;
        acc = x0;
        e++;
    }
    for (; e < end; e += 2) {
        int s0 = g_esrc[e], s1 = g_esrc[e + 1];
        float4 x0 = load_xl(xlh, s0, lane);
        float4 x1 = load_xl(xlh, s1, lane);
        float a0 = x0.x + xr.x, a1 = x0.y + xr.y, a2 = x0.z + xr.z, a3 = x0.w + xr.w;
        float b0 = x1.x + xr.x, b1 = x1.y + xr.y, b2 = x1.z + xr.z, b3 = x1.w + xr.w;
        float p0 = ((a0 > 0.f) ? a0 : 0.2f * a0) * at.x + ((a1 > 0.f) ? a1 : 0.2f * a1) * at.y
                 + ((a2 > 0.f) ? a2 : 0.2f * a2) * at.z + ((a3 > 0.f) ? a3 : 0.2f * a3) * at.w;
        float p1 = ((b0 > 0.f) ? b0 : 0.2f * b0) * at.x + ((b1 > 0.f) ? b1 : 0.2f * b1) * at.y
                 + ((b2 > 0.f) ? b2 : 0.2f * b2) * at.z + ((b3 > 0.f) ? b3 : 0.2f * b3) * at.w;
        p0 += __shfl_xor_sync(0xffffffffu, p0, 1);
        p1 += __shfl_xor_sync(0xffffffffu, p1, 1);
        p0 += __shfl_xor_sync(0xffffffffu, p0, 2);
        p1 += __shfl_xor_sync(0xffffffffu, p1, 2);
        p0 += __shfl_xor_sync(0xffffffffu, p0, 4);
        p1 += __shfl_xor_sync(0xffffffffu, p1, 4);
        float nm = fmaxf(m, fmaxf(p0, p1));
        float corr = __expf(m - nm);
        float w0 = __expf(p0 - nm);
        float w1 = __expf(p1 - nm);
        ssum = ssum * corr + w0 + w1;
        acc.x = acc.x * corr + w0 * x0.x + w1 * x1.x;
        acc.y = acc.y * corr + w0 * x0.y + w1 * x1.y;
        acc.z = acc.z * corr + w0 * x0.z + w1 * x1.z;
        acc.w = acc.w * corr + w0 * x0.w + w1 * x1.w;
        m = nm;
    }
    float inv = 1.f / ssum;
    float4 gb4 = ((const float4*)gb)[lane];
    float4 id = ((const float4*)g_h)[(size_t)gw * 32 + lane];
    float4 o;
    o.x = fmaxf(acc.x * inv + gb4.x, 0.f) + id.x;
    o.y = fmaxf(acc.y * inv + gb4.y, 0.f) + id.y;
    o.z = fmaxf(acc.z * inv + gb4.z, 0.f) + id.z;
    o.w = fmaxf(acc.w * inv + gb4.w, 0.f) + id.w;
    ((float4*)g_h)[(size_t)gw * 32 + lane] = o;
}

// ---------------- fused classification + h copy (warp per row, conflict-free) ----
__global__ void class_copy_kernel(const float* __restrict__ Wc, const float* __restrict__ bc,
                                  float* __restrict__ out) {
    __shared__ float sW[16][128];
    __shared__ float sbc[16];
    int t = threadIdx.x;
    for (int i = t; i < 2048; i += 256) {
        int k = i >> 4, j = i & 15;
        sW[j][k] = Wc[i];          // Wc row-major [k][j]
    }
    if (t < 16) sbc[t] = bc[t];
    __syncthreads();

    int gw = (blockIdx.x * blockDim.x + t) >> 5;
    int lane = t & 31;
    if (gw >= NN) return;
    float4 h4 = ((const float4*)g_h)[(size_t)gw * 32 + lane];
    ((float4*)(out + (size_t)NN * 16))[(size_t)gw * 32 + lane] = h4;

    float p[16];
#pragma unroll
    for (int j = 0; j < 16; j++) {
        float4 w = *(const float4*)&sW[j][lane * 4];
        p[j] = h4.x * w.x + h4.y * w.y + h4.z * w.z + h4.w * w.w;
    }
#pragma unroll
    for (int sh = 16; sh > 0; sh >>= 1)
#pragma unroll
        for (int j = 0; j < 16; j++)
            p[j] += __shfl_xor_sync(0xffffffffu, p[j], sh);
    if (lane < 16) out[(size_t)gw * 16 + lane] = p[lane] + sbc[lane];
}

// ---------------- launcher ----------------
extern "C" void kernel_launch(void* const* d_in, const int* in_sizes, int n_in,
                              void* d_out, int out_size) {
    const float* x    = (const float*)d_in[0];
    const int*   ei   = (const int*)  d_in[1];
    const float* Wp   = (const float*)d_in[2];
    const float* bp   = (const float*)d_in[3];
    const float* ln_g = (const float*)d_in[4];
    const float* ln_b = (const float*)d_in[5];
    const float* Wl   = (const float*)d_in[6];
    const float* bl   = (const float*)d_in[7];
    const float* Wr   = (const float*)d_in[8];
    const float* br   = (const float*)d_in[9];
    const float* att  = (const float*)d_in[10];
    const float* gb   = (const float*)d_in[11];
    const float* Wc   = (const float*)d_in[12];
    const float* bc   = (const float*)d_in[13];
    float* out = (float*)d_out;

    const int SMEM_BYTES = 4 * SMAT * 2;   // 139264 B
    cudaFuncSetAttribute(mma_gemm_kernel, cudaFuncAttributeMaxDynamicSharedMemorySize, SMEM_BYTES);

    // CSR by destination (coalesced 3-pass scan; self-loops in scan3)
    zero_cnt_kernel<<<(NN + 255) / 256, 256>>>();
    hist_kernel<<<EE / 256, 256>>>(ei);
    scan1_kernel<<<SCAN_B, 256>>>();
    scan2_kernel<<<1, 512>>>();
    scan3_kernel<<<SCAN_B, 256>>>();
    scatter_kernel<<<EE / 256, 256>>>(ei);

    // weight + input conversion
    convert_w_kernel<<<(5 * 16384 + 255) / 256, 256>>>(Wp, Wl, Wr);
    convert_x_kernel<<<(NN * 32 + 255) / 256, 256>>>(x);

    const int GG = (NN + 127) / 128;
    // h = x @ Wp + bp
    mma_gemm_kernel<<<GG, 256, SMEM_BYTES>>>(0, bp, 0);

    for (int l = 0; l < 2; l++) {
        ln_kernel<<<(NN * 32 + 255) / 256, 256>>>(ln_g + l * 128, ln_b + l * 128);
        mma_gemm_kernel<<<GG, 256, SMEM_BYTES>>>(1 + 2 * l, bl + l * 128, 1);
        mma_gemm_kernel<<<GG, 256, SMEM_BYTES>>>(2 + 2 * l, br + l * 128, 2);
        edge_kernel<<<(NN * 32 + 255) / 256, 256>>>(att + l * 128, gb + l * 128);
    }

    class_copy_kernel<<<(NN * 32 + 255) / 256, 256>>>(Wc, bc, out);
}